// round 14
// baseline (speedup 1.0000x reference)
#include <cuda_runtime.h>
#include <cuda_fp16.h>
#include <cstdint>
#include <math.h>

// Problem constants
#define B_  1
#define S_  2048
#define H_  2048
#define NH_ 8
#define DH_ 256
#define SCALE_ 0.0625f   // 256^-0.5
#define NEG_  -1000000000.0f

typedef __half fp16;

// ================= helpers =====================================================
__device__ __forceinline__ uint32_t smem_to_u32(const void* smem_ptr) {
    uint32_t addr;
    asm("{ .reg .u64 tmp; cvta.to.shared.u64 tmp, %1; cvt.u32.u64 %0, tmp; }"
        : "=r"(addr) : "l"(smem_ptr));
    return addr;
}

__device__ __forceinline__ void cp_async16(uint32_t dst, const void* src) {
    asm volatile("cp.async.cg.shared.global [%0], [%1], 16;\n"
                 :: "r"(dst), "l"(src) : "memory");
}

__device__ __forceinline__ void ldsm_x4(uint32_t r[4], uint32_t addr) {
    asm volatile("ldmatrix.sync.aligned.m8n8.x4.shared.b16 {%0,%1,%2,%3}, [%4];"
                 : "=r"(r[0]), "=r"(r[1]), "=r"(r[2]), "=r"(r[3]) : "r"(addr));
}

__device__ __forceinline__ void mma_fp16(float acc[4], const uint32_t a[4], const uint32_t b[2]) {
    asm volatile(
        "mma.sync.aligned.m16n8k16.row.col.f32.f16.f16.f32 "
        "{%0,%1,%2,%3}, {%4,%5,%6,%7}, {%8,%9}, {%0,%1,%2,%3};"
        : "+f"(acc[0]), "+f"(acc[1]), "+f"(acc[2]), "+f"(acc[3])
        : "r"(a[0]), "r"(a[1]), "r"(a[2]), "r"(a[3]), "r"(b[0]), "r"(b[1]));
}

__device__ __forceinline__ uint32_t pack_h2(float v0, float v1) {
    fp16 h0 = __float2half(v0);
    fp16 h1 = __float2half(v1);
    return (uint32_t)__half_as_ushort(h0) | ((uint32_t)__half_as_ushort(h1) << 16);
}
__device__ __forceinline__ uint32_t pack_l2(float v0, float v1) {
    fp16 h0 = __float2half(v0);
    fp16 h1 = __float2half(v1);
    fp16 l0 = __float2half(v0 - __half2float(h0));
    fp16 l1 = __float2half(v1 - __half2float(h1));
    return (uint32_t)__half_as_ushort(l0) | ((uint32_t)__half_as_ushort(l1) << 16);
}
__device__ __forceinline__ uint2 pack_h4(float a, float b, float c, float d) {
    return make_uint2(pack_h2(a, b), pack_h2(c, d));
}
__device__ __forceinline__ uint2 pack_l4(float a, float b, float c, float d) {
    return make_uint2(pack_l2(a, b), pack_l2(c, d));
}

// ================= scratch (device globals; no allocation) ====================
__device__ __align__(128) float g_Q  [S_ * H_];
__device__ __align__(128) float g_K  [S_ * DH_];
__device__ __align__(128) float g_V  [S_ * DH_];

__device__ __align__(128) fp16 g_xh  [S_ * H_];
__device__ __align__(128) fp16 g_wqT [H_ * H_];
__device__ __align__(128) fp16 g_wkT [DH_ * H_];
__device__ __align__(128) fp16 g_wvT [DH_ * H_];
__device__ __align__(128) fp16 g_woT [H_ * H_];
__device__ __align__(128) fp16 g_qh  [S_ * H_];
__device__ __align__(128) fp16 g_khi [S_ * DH_];
__device__ __align__(128) fp16 g_klo [S_ * DH_];
__device__ __align__(128) fp16 g_vt  [DH_ * S_];
__device__ __align__(128) fp16 g_ph  [(long long)NH_ * S_ * S_];
__device__ __align__(128) fp16 g_ch  [S_ * H_];

// ================= fp16 mma.sync GEMM, K-chunk 32, 4-stage pipeline ===========
// NPASS=1: A@B (both single); NPASS=2: A@(Bhi+Blo) (QK).
// Each stage holds TWO 16-wide sub-tiles per operand (conflict-free ROW=24).
// One __syncthreads per 32-K stage; next stage's cp.async issued right after it.
template<int NT8, int NPASS>
__global__ __launch_bounds__(256, 2)
void mma_gemm(const fp16* __restrict__ A_, const fp16* __restrict__ Bhi,
              const fp16* __restrict__ Blo,
              float* __restrict__ C, fp16* __restrict__ Ch,
              int K, int lda, int ldb, int ldc,
              long long aStride, long long bStride, long long cStride,
              int mode)
{
    constexpr int TN     = NT8 * 32;
    constexpr int ROW    = 24;                 // fp16 per smem row (48B)
    constexpr int A_SUB  = 128 * ROW;          // one 16-wide A sub-tile (elems)
    constexpr int B_SUB  = TN * ROW;
    constexpr int NB     = (NPASS >= 2) ? 2 : 1;
    constexpr int STAGE  = 2 * (A_SUB + NB * B_SUB);   // 2 sub-chunks per stage

    const int rowBase = blockIdx.y * 128;
    const int colBase = blockIdx.x * TN;

    if ((mode & 1) && colBase > rowBase + 127) return;

    int Keff = K;
    if (mode & 2) Keff = min(K, rowBase + 128);

    extern __shared__ fp16 smem[];
    const uint32_t sbase = smem_to_u32(smem);

    const int tid  = threadIdx.x;
    const int wid  = tid >> 5;
    const int lane = tid & 31;
    const int wm   = wid & 1;
    const int wn   = wid >> 1;

    A_  += (long long)blockIdx.z * aStride;
    Bhi += (long long)blockIdx.z * bStride;
    if (NPASS >= 2) Blo += (long long)blockIdx.z * bStride;

    float acc[4][NT8][4] = {};

    const int nStages = Keff >> 5;             // K-chunk = 32

    const int lrow = tid >> 1;                 // 0..127
    const int lch  = tid & 1;

    // loads one 32-K stage: two 16-wide sub-tiles per operand
    auto issue = [&](int s) {
        const uint32_t sb = sbase + (uint32_t)(s & 3) * STAGE * 2;
        const int kt = s << 5;
        #pragma unroll
        for (int half = 0; half < 2; half++) {
            const uint32_t hb = sb + (uint32_t)half * (A_SUB + NB * B_SUB) * 2;
            const int kh = kt + half * 16;
            {
                const long long g = (long long)(rowBase + lrow) * lda + kh + lch * 8;
                const uint32_t d = hb + (uint32_t)(lrow * ROW + lch * 8) * 2;
                cp_async16(d, A_ + g);
            }
            if (TN == 128 || tid < 128) {
                const long long g = (long long)(colBase + lrow) * ldb + kh + lch * 8;
                const uint32_t d = hb + (uint32_t)(A_SUB + lrow * ROW + lch * 8) * 2;
                cp_async16(d, Bhi + g);
                if (NPASS >= 2) cp_async16(d + B_SUB * 2, Blo + g);
            }
        }
        asm volatile("cp.async.commit_group;\n" ::: "memory");
    };

    issue(0);
    if (1 < nStages) issue(1);
    if (2 < nStages) issue(2);

    for (int s = 0; s < nStages; s++) {
        const int remain = nStages - 1 - s;
        if (remain >= 2)      asm volatile("cp.async.wait_group 2;\n" ::: "memory");
        else if (remain == 1) asm volatile("cp.async.wait_group 1;\n" ::: "memory");
        else                  asm volatile("cp.async.wait_group 0;\n" ::: "memory");
        __syncthreads();

        // issue next stage's loads ASAP (buffer (s+3)&3 freed by this barrier)
        if (s + 3 < nStages) issue(s + 3);

        const uint32_t sb = sbase + (uint32_t)(s & 3) * STAGE * 2;

        const int arow = wm * 64 + (lane & 15);
        const int acol = ((lane >> 4) << 3);
        const int brow4 = wn * (NT8 * 8) + ((lane >> 4) << 3) + (lane & 7);
        const int bcol4 = (((lane >> 3) & 1) << 3);

        #pragma unroll
        for (int half = 0; half < 2; half++) {
            const uint32_t hb = sb + (uint32_t)half * (A_SUB + NB * B_SUB) * 2;
            const uint32_t sA = hb;
            const uint32_t sB = hb + A_SUB * 2;

            uint32_t bh[NT8][2], bl[NT8][2];
            #pragma unroll
            for (int ntp = 0; ntp < NT8 / 2; ntp++) {
                const uint32_t addr =
                    sB + (uint32_t)((brow4 + ntp * 16) * ROW + bcol4) * 2;
                uint32_t rh[4];
                ldsm_x4(rh, addr);
                bh[2 * ntp][0] = rh[0]; bh[2 * ntp][1] = rh[1];
                bh[2 * ntp + 1][0] = rh[2]; bh[2 * ntp + 1][1] = rh[3];
                if (NPASS >= 2) {
                    uint32_t rl[4];
                    ldsm_x4(rl, addr + B_SUB * 2);
                    bl[2 * ntp][0] = rl[0]; bl[2 * ntp][1] = rl[1];
                    bl[2 * ntp + 1][0] = rl[2]; bl[2 * ntp + 1][1] = rl[3];
                }
            }
            uint32_t ah[4][4];
            #pragma unroll
            for (int mt = 0; mt < 4; mt++) {
                const uint32_t addr = sA + (uint32_t)((arow + mt * 16) * ROW + acol) * 2;
                ldsm_x4(ah[mt], addr);
            }
            #pragma unroll
            for (int mt = 0; mt < 4; mt++)
                #pragma unroll
                for (int nt = 0; nt < NT8; nt++)
                    mma_fp16(acc[mt][nt], ah[mt], bh[nt]);
            if (NPASS >= 2) {
                #pragma unroll
                for (int mt = 0; mt < 4; mt++)
                    #pragma unroll
                    for (int nt = 0; nt < NT8; nt++)
                        mma_fp16(acc[mt][nt], ah[mt], bl[nt]);
            }
        }
    }

    const int erow0 = rowBase + wm * 64 + (lane >> 2);
    const int ecol0 = colBase + wn * (NT8 * 8) + (lane & 3) * 2;
    #pragma unroll
    for (int mt = 0; mt < 4; mt++) {
        #pragma unroll
        for (int nt = 0; nt < NT8; nt++) {
            const int r = erow0 + mt * 16;
            const int c = ecol0 + nt * 8;
            if (C) {
                float* Cb = C + (long long)blockIdx.z * cStride;
                *(float2*)&Cb[(long long)r * ldc + c] =
                    make_float2(acc[mt][nt][0], acc[mt][nt][1]);
                *(float2*)&Cb[(long long)(r + 8) * ldc + c] =
                    make_float2(acc[mt][nt][2], acc[mt][nt][3]);
            }
            if (Ch) {
                fp16* Hb = Ch + (long long)blockIdx.z * cStride;
                *(uint32_t*)&Hb[(long long)r * ldc + c] = pack_h2(acc[mt][nt][0], acc[mt][nt][1]);
                *(uint32_t*)&Hb[(long long)(r + 8) * ldc + c] = pack_h2(acc[mt][nt][2], acc[mt][nt][3]);
            }
        }
    }
}

// ================= fp32 -> fp16 single convert (float4 vectorized) ============
__global__ void convert_kernel(const float4* __restrict__ in,
                               uint2* __restrict__ h, long long n4)
{
    long long i = (long long)blockIdx.x * blockDim.x + threadIdx.x;
    if (i >= n4) return;
    float4 v = in[i];
    h[i] = pack_h4(v.x, v.y, v.z, v.w);
}

// transpose + convert: in[R][C] fp32 -> hT [C][R] single fp16
__global__ void tconvert_kernel(const float* __restrict__ in,
                                fp16* __restrict__ hT, int R, int C)
{
    __shared__ float tile[32][36];
    const int c0 = blockIdx.x * 32;
    const int r0 = blockIdx.y * 32;
    const int tx = threadIdx.x;
    const int ty = threadIdx.y;

    {
        float4 v = *(const float4*)&in[(long long)(r0 + tx) * C + c0 + ty * 4];
        *(float4*)&tile[tx][ty * 4] = v;
    }
    __syncthreads();
    {
        float a = tile[ty * 4 + 0][tx];
        float b = tile[ty * 4 + 1][tx];
        float c = tile[ty * 4 + 2][tx];
        float d = tile[ty * 4 + 3][tx];
        const long long o = (long long)(c0 + tx) * R + r0 + ty * 4;
        *(uint2*)&hT[o] = pack_h4(a, b, c, d);
    }
}

// ================= RoPE (fp32 in -> fp16 hi [+lo] out) ========================
__global__ void rope_split_kernel(const float* __restrict__ src,
                                  fp16* __restrict__ hi, fp16* __restrict__ lo,
                                  const int* __restrict__ pos,
                                  int nHeads, int rowStride)
{
    long long idx = (long long)blockIdx.x * blockDim.x + threadIdx.x;
    const long long total = (long long)S_ * nHeads * 32;
    if (idx >= total) return;
    const int d4 = (int)(idx & 31) * 4;
    const int h  = (int)((idx >> 5) % nHeads);
    const int s  = (int)(idx / (32LL * nHeads));

    const float p = (float)pos[s];
    const long long base = (long long)s * rowStride + h * DH_;

    float4 a = *(const float4*)&src[base + d4];
    float4 b = *(const float4*)&src[base + d4 + 128];

    float ra[4], rb[4];
    const float av[4] = {a.x, a.y, a.z, a.w};
    const float bv[4] = {b.x, b.y, b.z, b.w};
    #pragma unroll
    for (int k = 0; k < 4; k++) {
        const int d = d4 + k;
        float inv = exp2f(-((float)(2 * d) / (float)DH_) * log2f(10000.0f));
        float ang = p * inv;
        float sn, cs;
        sincosf(ang, &sn, &cs);
        ra[k] = av[k] * cs - bv[k] * sn;
        rb[k] = bv[k] * cs + av[k] * sn;
    }

    *(uint2*)&hi[base + d4]       = pack_h4(ra[0], ra[1], ra[2], ra[3]);
    *(uint2*)&hi[base + d4 + 128] = pack_h4(rb[0], rb[1], rb[2], rb[3]);
    if (lo) {
        *(uint2*)&lo[base + d4]       = pack_l4(ra[0], ra[1], ra[2], ra[3]);
        *(uint2*)&lo[base + d4 + 128] = pack_l4(rb[0], rb[1], rb[2], rb[3]);
    }
}

// ================= causal scale + softmax (fp32 out + single fp16 P) ==========
__global__ void softmax_kernel(float* __restrict__ attn, fp16* __restrict__ ph)
{
    const int i = blockIdx.x;
    const int h = blockIdx.y;
    const long long rowOff = ((long long)h * S_ + i) * S_;
    float* row = attn + rowOff;
    const int t = threadIdx.x;
    const int lane = t & 31, warp = t >> 5;

    const int kLimit = ((i >> 7) + 1) << 7;

    float vals[8];
    float mx = -INFINITY;
    #pragma unroll
    for (int j = 0; j < 2; j++) {
        const int col4 = 4 * t + j * 1024;
        if (col4 <= i) {
            float4 v = *(const float4*)&row[col4];
            const float vv[4] = {v.x, v.y, v.z, v.w};
            #pragma unroll
            for (int k = 0; k < 4; k++) {
                const int col = col4 + k;
                float u = (col <= i) ? fmaf(vv[k], SCALE_, 0.0f) : NEG_;
                vals[j * 4 + k] = u;
                mx = fmaxf(mx, u);
            }
        } else {
            #pragma unroll
            for (int k = 0; k < 4; k++) vals[j * 4 + k] = NEG_;
        }
    }

    __shared__ float red[8];
    #pragma unroll
    for (int o = 16; o > 0; o >>= 1)
        mx = fmaxf(mx, __shfl_xor_sync(0xffffffffu, mx, o));
    if (lane == 0) red[warp] = mx;
    __syncthreads();
    {
        float m = red[lane & 7];
        #pragma unroll
        for (int o = 4; o > 0; o >>= 1)
            m = fmaxf(m, __shfl_xor_sync(0xffffffffu, m, o));
        mx = m;
    }

    float sum = 0.0f;
    #pragma unroll
    for (int j = 0; j < 8; j++) {
        vals[j] = __expf(vals[j] - mx);
        sum += vals[j];
    }
    #pragma unroll
    for (int o = 16; o > 0; o >>= 1)
        sum += __shfl_xor_sync(0xffffffffu, sum, o);
    __syncthreads();
    if (lane == 0) red[warp] = sum;
    __syncthreads();
    {
        float m = red[lane & 7];
        #pragma unroll
        for (int o = 4; o > 0; o >>= 1)
            m += __shfl_xor_sync(0xffffffffu, m, o);
        sum = m;
    }

    const float inv = 1.0f / sum;
    #pragma unroll
    for (int j = 0; j < 2; j++) {
        const int col4 = 4 * t + j * 1024;
        float p0 = vals[j * 4 + 0] * inv;
        float p1 = vals[j * 4 + 1] * inv;
        float p2 = vals[j * 4 + 2] * inv;
        float p3 = vals[j * 4 + 3] * inv;
        *(float4*)&row[col4] = make_float4(p0, p1, p2, p3);
        if (col4 < kLimit)
            *(uint2*)&ph[rowOff + col4] = pack_h4(p0, p1, p2, p3);
    }
}

// ================= launch ======================================================
static void* sym_addr(const void* sym)
{
    void* p = nullptr;
    cudaGetSymbolAddress(&p, sym);
    return p;
}

extern "C" void kernel_launch(void* const* d_in, const int* in_sizes, int n_in,
                              void* d_out, int out_size)
{
    const float* x    = (const float*)d_in[0];
    const int*   pos  = (const int*)  d_in[1];
    const float* wq   = (const float*)d_in[3];
    const float* wk   = (const float*)d_in[4];
    const float* wv   = (const float*)d_in[5];
    const float* wo   = (const float*)d_in[6];

    float* out  = (float*)d_out;
    float* attn = out + (long long)B_ * S_ * H_;

    float* Qf = (float*)sym_addr(g_Q);
    float* Kf = (float*)sym_addr(g_K);
    float* Vf = (float*)sym_addr(g_V);

    fp16* xh   = (fp16*)sym_addr(g_xh);
    fp16* wqT  = (fp16*)sym_addr(g_wqT);
    fp16* wkT  = (fp16*)sym_addr(g_wkT);
    fp16* wvT  = (fp16*)sym_addr(g_wvT);
    fp16* woT  = (fp16*)sym_addr(g_woT);
    fp16* qh   = (fp16*)sym_addr(g_qh);
    fp16* khi  = (fp16*)sym_addr(g_khi);
    fp16* klo  = (fp16*)sym_addr(g_klo);
    fp16* vt   = (fp16*)sym_addr(g_vt);
    fp16* ph   = (fp16*)sym_addr(g_ph);
    fp16* ch   = (fp16*)sym_addr(g_ch);

    // smem: 4 stages, K-chunk 32 (2 sub-tiles per stage)
    const int smem1p128 = 4 * 2 * (128 * 24 + 128 * 24) * 2;          // 98304
    const int smem1p64  = 4 * 2 * (128 * 24 +  64 * 24) * 2;          // 73728
    const int smem2p128 = 4 * 2 * (128 * 24 + 2 * 128 * 24) * 2;      // 147456 -> too big for 2 CTA; use 3 stages
    // 2-pass QK: 3 stages fit 110592, still > 114688/CTA? 228KB/2 = 114KB ok
    const int smem2p128_3 = 3 * 2 * (128 * 24 + 2 * 128 * 24) * 2;    // 110592
    cudaFuncSetAttribute(mma_gemm<4,1>, cudaFuncAttributeMaxDynamicSharedMemorySize, smem1p128);
    cudaFuncSetAttribute(mma_gemm<2,1>, cudaFuncAttributeMaxDynamicSharedMemorySize, smem1p64);
    cudaFuncSetAttribute(mma_gemm<4,2>, cudaFuncAttributeMaxDynamicSharedMemorySize, smem2p128);

    const long long SS  = (long long)S_ * S_;
    const long long nSH = (long long)S_ * H_;

    // ---- prep: Q-proj GEMM stays at launch #3 for ncu capture ----
    convert_kernel<<<(unsigned)((nSH / 4 + 255) / 256), 256>>>(
        (const float4*)x, (uint2*)xh, nSH / 4);
    tconvert_kernel<<<dim3(H_ / 32,  H_ / 32), dim3(32, 8)>>>(wq, wqT, H_, H_);
    tconvert_kernel<<<dim3(DH_ / 32, H_ / 32), dim3(32, 8)>>>(wk, wkT, H_, DH_);

    // ---- Q-proj (1-pass): launch #3 ----
    mma_gemm<4,1><<<dim3(H_ / 128, S_ / 128, 1), 256, smem1p128>>>(
        xh, wqT, nullptr, Qf, nullptr, H_, H_, H_, H_, 0, 0, 0, 0);

    tconvert_kernel<<<dim3(DH_ / 32, H_ / 32), dim3(32, 8)>>>(wv, wvT, H_, DH_);
    {
        const long long bS = (long long)(wvT - wkT);
        const long long cS = (long long)(Vf - Kf);
        mma_gemm<2,1><<<dim3(DH_ / 64, S_ / 128, 2), 256, smem1p64>>>(
            xh, wkT, nullptr, Kf, nullptr, H_, H_, H_, DH_, 0, bS, cS, 0);
    }

    // ---- RoPE: Q -> single fp16; K -> hi/lo (for 2-pass QK) ----
    rope_split_kernel<<<(unsigned)(((long long)S_ * NH_ * 32 + 255) / 256), 256>>>(
        Qf, qh, nullptr, pos, NH_, H_);
    rope_split_kernel<<<(unsigned)(((long long)S_ * 32 + 255) / 256), 256>>>(
        Kf, khi, klo, pos, 1, DH_);

    // ---- V transpose (single fp16) ----
    tconvert_kernel<<<dim3(DH_ / 32, S_ / 32), dim3(32, 8)>>>(Vf, vt, S_, DH_);

    // ---- scores: attn_h = Q_h @ K^T (2-pass: Q@Khi + Q@Klo, causal skip) ----
    mma_gemm<4,2><<<dim3(S_ / 128, S_ / 128, NH_), 256, smem2p128>>>(
        qh, khi, klo, attn, nullptr, DH_, H_, DH_, S_, DH_, 0, SS, 1);

    // ---- softmax (analytic causal mask, single fp16 P) ----
    softmax_kernel<<<dim3(S_, NH_), 256>>>(attn, ph);

    // ---- ctx_h = P_h @ V (1-pass, causal K-limit, fp16 ctx epilogue) ----
    mma_gemm<4,1><<<dim3(DH_ / 128, S_ / 128, NH_), 256, smem1p128>>>(
        ph, vt, nullptr, nullptr, ch, S_, S_, S_, H_, SS, 0, DH_, 2);

    // ---- wo transpose, then out = ctx @ w_o (1-pass) ----
    tconvert_kernel<<<dim3(H_ / 32, H_ / 32), dim3(32, 8)>>>(wo, woT, H_, H_);
    mma_gemm<4,1><<<dim3(H_ / 128, S_ / 128, 1), 256, smem1p128>>>(
        ch, woT, nullptr, out, nullptr, H_, H_, H_, H_, 0, 0, 0, 0);
}

// round 15
// speedup vs baseline: 1.1852x; 1.1852x over previous
#include <cuda_runtime.h>
#include <cuda_fp16.h>
#include <cstdint>
#include <math.h>

// Problem constants
#define B_  1
#define S_  2048
#define H_  2048
#define NH_ 8
#define DH_ 256
#define SCALE_ 0.0625f   // 256^-0.5
#define NEG_  -1000000000.0f

typedef __half fp16;

// ================= helpers =====================================================
__device__ __forceinline__ uint32_t smem_to_u32(const void* smem_ptr) {
    uint32_t addr;
    asm("{ .reg .u64 tmp; cvta.to.shared.u64 tmp, %1; cvt.u32.u64 %0, tmp; }"
        : "=r"(addr) : "l"(smem_ptr));
    return addr;
}

__device__ __forceinline__ void cp_async16(uint32_t dst, const void* src) {
    asm volatile("cp.async.cg.shared.global [%0], [%1], 16;\n"
                 :: "r"(dst), "l"(src) : "memory");
}

__device__ __forceinline__ void ldsm_x4(uint32_t r[4], uint32_t addr) {
    asm volatile("ldmatrix.sync.aligned.m8n8.x4.shared.b16 {%0,%1,%2,%3}, [%4];"
                 : "=r"(r[0]), "=r"(r[1]), "=r"(r[2]), "=r"(r[3]) : "r"(addr));
}

__device__ __forceinline__ void mma_fp16(float acc[4], const uint32_t a[4], const uint32_t b[2]) {
    asm volatile(
        "mma.sync.aligned.m16n8k16.row.col.f32.f16.f16.f32 "
        "{%0,%1,%2,%3}, {%4,%5,%6,%7}, {%8,%9}, {%0,%1,%2,%3};"
        : "+f"(acc[0]), "+f"(acc[1]), "+f"(acc[2]), "+f"(acc[3])
        : "r"(a[0]), "r"(a[1]), "r"(a[2]), "r"(a[3]), "r"(b[0]), "r"(b[1]));
}

__device__ __forceinline__ uint32_t pack_h2(float v0, float v1) {
    fp16 h0 = __float2half(v0);
    fp16 h1 = __float2half(v1);
    return (uint32_t)__half_as_ushort(h0) | ((uint32_t)__half_as_ushort(h1) << 16);
}
__device__ __forceinline__ uint32_t pack_l2(float v0, float v1) {
    fp16 h0 = __float2half(v0);
    fp16 h1 = __float2half(v1);
    fp16 l0 = __float2half(v0 - __half2float(h0));
    fp16 l1 = __float2half(v1 - __half2float(h1));
    return (uint32_t)__half_as_ushort(l0) | ((uint32_t)__half_as_ushort(l1) << 16);
}
__device__ __forceinline__ uint2 pack_h4(float a, float b, float c, float d) {
    return make_uint2(pack_h2(a, b), pack_h2(c, d));
}
__device__ __forceinline__ uint2 pack_l4(float a, float b, float c, float d) {
    return make_uint2(pack_l2(a, b), pack_l2(c, d));
}

// ================= scratch (device globals; no allocation) ====================
__device__ __align__(128) float g_Q  [S_ * H_];
__device__ __align__(128) float g_K  [S_ * DH_];
__device__ __align__(128) float g_V  [S_ * DH_];

__device__ __align__(128) fp16 g_xh  [S_ * H_];
__device__ __align__(128) fp16 g_wqT [H_ * H_];
__device__ __align__(128) fp16 g_wkT [DH_ * H_];
__device__ __align__(128) fp16 g_wvT [DH_ * H_];
__device__ __align__(128) fp16 g_woT [H_ * H_];
__device__ __align__(128) fp16 g_qh  [S_ * H_];
__device__ __align__(128) fp16 g_khi [S_ * DH_];
__device__ __align__(128) fp16 g_klo [S_ * DH_];
__device__ __align__(128) fp16 g_vt  [DH_ * S_];
__device__ __align__(128) fp16 g_ph  [(long long)NH_ * S_ * S_];
__device__ __align__(128) fp16 g_ch  [S_ * H_];

// ================= fp16 mma.sync GEMM, K-chunk 16, 4-stage pipeline ===========
// (R13 configuration — best known — with prefetch hoisted above compute.)
// NPASS=1: A@B (both single); NPASS=2: A@(Bhi+Blo) (QK).
template<int NT8, int NPASS>
__global__ __launch_bounds__(256, 2)
void mma_gemm(const fp16* __restrict__ A_, const fp16* __restrict__ Bhi,
              const fp16* __restrict__ Blo,
              float* __restrict__ C, fp16* __restrict__ Ch,
              int K, int lda, int ldb, int ldc,
              long long aStride, long long bStride, long long cStride,
              int mode)
{
    constexpr int TN     = NT8 * 32;
    constexpr int ROW    = 24;                 // fp16 per smem row (48B, conflict-free)
    constexpr int A_TILE = 128 * ROW;
    constexpr int B_TILE = TN * ROW;
    constexpr int NB     = (NPASS >= 2) ? 2 : 1;
    constexpr int STAGE  = A_TILE + NB * B_TILE;

    const int rowBase = blockIdx.y * 128;
    const int colBase = blockIdx.x * TN;

    if ((mode & 1) && colBase > rowBase + 127) return;

    int Keff = K;
    if (mode & 2) Keff = min(K, rowBase + 128);

    extern __shared__ fp16 smem[];
    const uint32_t sbase = smem_to_u32(smem);

    const int tid  = threadIdx.x;
    const int wid  = tid >> 5;
    const int lane = tid & 31;
    const int wm   = wid & 1;
    const int wn   = wid >> 1;

    A_  += (long long)blockIdx.z * aStride;
    Bhi += (long long)blockIdx.z * bStride;
    if (NPASS >= 2) Blo += (long long)blockIdx.z * bStride;

    float acc[4][NT8][4] = {};

    const int nStages = Keff >> 4;             // K-chunk = 16

    const int lrow = tid >> 1;
    const int lch  = tid & 1;

    auto issue = [&](int s) {
        const uint32_t sb = sbase + (uint32_t)(s & 3) * STAGE * 2;
        const int kt = s << 4;
        {
            const long long g = (long long)(rowBase + lrow) * lda + kt + lch * 8;
            const uint32_t d = sb + (uint32_t)(lrow * ROW + lch * 8) * 2;
            cp_async16(d, A_ + g);
        }
        if (TN == 128 || tid < 128) {
            const long long g = (long long)(colBase + lrow) * ldb + kt + lch * 8;
            const uint32_t d = sb + (uint32_t)(A_TILE + lrow * ROW + lch * 8) * 2;
            cp_async16(d, Bhi + g);
            if (NPASS >= 2) cp_async16(d + B_TILE * 2, Blo + g);
        }
        asm volatile("cp.async.commit_group;\n" ::: "memory");
    };

    issue(0);
    if (1 < nStages) issue(1);
    if (2 < nStages) issue(2);

    for (int s = 0; s < nStages; s++) {
        const int remain = nStages - 1 - s;
        if (remain >= 2)      asm volatile("cp.async.wait_group 2;\n" ::: "memory");
        else if (remain == 1) asm volatile("cp.async.wait_group 1;\n" ::: "memory");
        else                  asm volatile("cp.async.wait_group 0;\n" ::: "memory");
        __syncthreads();

        // hoisted prefetch: buffer (s+3)&3 was freed by the barrier above
        if (s + 3 < nStages) issue(s + 3);

        const uint32_t sb = sbase + (uint32_t)(s & 3) * STAGE * 2;
        const uint32_t sA = sb;
        const uint32_t sB = sb + A_TILE * 2;

        const int arow = wm * 64 + (lane & 15);
        const int acol = ((lane >> 4) << 3);
        const int brow4 = wn * (NT8 * 8) + ((lane >> 4) << 3) + (lane & 7);
        const int bcol4 = (((lane >> 3) & 1) << 3);

        // ---- B fragments (hi [+ lo]) ----
        uint32_t bh[NT8][2], bl[NT8][2];
        #pragma unroll
        for (int ntp = 0; ntp < NT8 / 2; ntp++) {
            const uint32_t addr =
                sB + (uint32_t)((brow4 + ntp * 16) * ROW + bcol4) * 2;
            uint32_t rh[4];
            ldsm_x4(rh, addr);
            bh[2 * ntp][0] = rh[0]; bh[2 * ntp][1] = rh[1];
            bh[2 * ntp + 1][0] = rh[2]; bh[2 * ntp + 1][1] = rh[3];
            if (NPASS >= 2) {
                uint32_t rl[4];
                ldsm_x4(rl, addr + B_TILE * 2);
                bl[2 * ntp][0] = rl[0]; bl[2 * ntp][1] = rl[1];
                bl[2 * ntp + 1][0] = rl[2]; bl[2 * ntp + 1][1] = rl[3];
            }
        }
        // ---- A fragments (single) ----
        uint32_t ah[4][4];
        #pragma unroll
        for (int mt = 0; mt < 4; mt++) {
            const uint32_t addr = sA + (uint32_t)((arow + mt * 16) * ROW + acol) * 2;
            ldsm_x4(ah[mt], addr);
        }
        // ---- MMA: pass-major (16 independent accumulators per pass) ----
        #pragma unroll
        for (int mt = 0; mt < 4; mt++)
            #pragma unroll
            for (int nt = 0; nt < NT8; nt++)
                mma_fp16(acc[mt][nt], ah[mt], bh[nt]);
        if (NPASS >= 2) {
            #pragma unroll
            for (int mt = 0; mt < 4; mt++)
                #pragma unroll
                for (int nt = 0; nt < NT8; nt++)
                    mma_fp16(acc[mt][nt], ah[mt], bl[nt]);
        }
    }

    const int erow0 = rowBase + wm * 64 + (lane >> 2);
    const int ecol0 = colBase + wn * (NT8 * 8) + (lane & 3) * 2;
    #pragma unroll
    for (int mt = 0; mt < 4; mt++) {
        #pragma unroll
        for (int nt = 0; nt < NT8; nt++) {
            const int r = erow0 + mt * 16;
            const int c = ecol0 + nt * 8;
            if (C) {
                float* Cb = C + (long long)blockIdx.z * cStride;
                *(float2*)&Cb[(long long)r * ldc + c] =
                    make_float2(acc[mt][nt][0], acc[mt][nt][1]);
                *(float2*)&Cb[(long long)(r + 8) * ldc + c] =
                    make_float2(acc[mt][nt][2], acc[mt][nt][3]);
            }
            if (Ch) {
                fp16* Hb = Ch + (long long)blockIdx.z * cStride;
                *(uint32_t*)&Hb[(long long)r * ldc + c] = pack_h2(acc[mt][nt][0], acc[mt][nt][1]);
                *(uint32_t*)&Hb[(long long)(r + 8) * ldc + c] = pack_h2(acc[mt][nt][2], acc[mt][nt][3]);
            }
        }
    }
}

// ================= fp32 -> fp16 single convert (float4 vectorized) ============
__global__ void convert_kernel(const float4* __restrict__ in,
                               uint2* __restrict__ h, long long n4)
{
    long long i = (long long)blockIdx.x * blockDim.x + threadIdx.x;
    if (i >= n4) return;
    float4 v = in[i];
    h[i] = pack_h4(v.x, v.y, v.z, v.w);
}

// transpose + convert: in[R][C] fp32 -> hT [C][R] single fp16
__global__ void tconvert_kernel(const float* __restrict__ in,
                                fp16* __restrict__ hT, int R, int C)
{
    __shared__ float tile[32][36];
    const int c0 = blockIdx.x * 32;
    const int r0 = blockIdx.y * 32;
    const int tx = threadIdx.x;
    const int ty = threadIdx.y;

    {
        float4 v = *(const float4*)&in[(long long)(r0 + tx) * C + c0 + ty * 4];
        *(float4*)&tile[tx][ty * 4] = v;
    }
    __syncthreads();
    {
        float a = tile[ty * 4 + 0][tx];
        float b = tile[ty * 4 + 1][tx];
        float c = tile[ty * 4 + 2][tx];
        float d = tile[ty * 4 + 3][tx];
        const long long o = (long long)(c0 + tx) * R + r0 + ty * 4;
        *(uint2*)&hT[o] = pack_h4(a, b, c, d);
    }
}

// ================= RoPE (fp32 in -> fp16 hi [+lo] out) ========================
__global__ void rope_split_kernel(const float* __restrict__ src,
                                  fp16* __restrict__ hi, fp16* __restrict__ lo,
                                  const int* __restrict__ pos,
                                  int nHeads, int rowStride)
{
    long long idx = (long long)blockIdx.x * blockDim.x + threadIdx.x;
    const long long total = (long long)S_ * nHeads * 32;
    if (idx >= total) return;
    const int d4 = (int)(idx & 31) * 4;
    const int h  = (int)((idx >> 5) % nHeads);
    const int s  = (int)(idx / (32LL * nHeads));

    const float p = (float)pos[s];
    const long long base = (long long)s * rowStride + h * DH_;

    float4 a = *(const float4*)&src[base + d4];
    float4 b = *(const float4*)&src[base + d4 + 128];

    float ra[4], rb[4];
    const float av[4] = {a.x, a.y, a.z, a.w};
    const float bv[4] = {b.x, b.y, b.z, b.w};
    #pragma unroll
    for (int k = 0; k < 4; k++) {
        const int d = d4 + k;
        float inv = exp2f(-((float)(2 * d) / (float)DH_) * log2f(10000.0f));
        float ang = p * inv;
        float sn, cs;
        sincosf(ang, &sn, &cs);
        ra[k] = av[k] * cs - bv[k] * sn;
        rb[k] = bv[k] * cs + av[k] * sn;
    }

    *(uint2*)&hi[base + d4]       = pack_h4(ra[0], ra[1], ra[2], ra[3]);
    *(uint2*)&hi[base + d4 + 128] = pack_h4(rb[0], rb[1], rb[2], rb[3]);
    if (lo) {
        *(uint2*)&lo[base + d4]       = pack_l4(ra[0], ra[1], ra[2], ra[3]);
        *(uint2*)&lo[base + d4 + 128] = pack_l4(rb[0], rb[1], rb[2], rb[3]);
    }
}

// ================= causal scale + softmax (fp32 out + single fp16 P) ==========
__global__ void softmax_kernel(float* __restrict__ attn, fp16* __restrict__ ph)
{
    const int i = blockIdx.x;
    const int h = blockIdx.y;
    const long long rowOff = ((long long)h * S_ + i) * S_;
    float* row = attn + rowOff;
    const int t = threadIdx.x;
    const int lane = t & 31, warp = t >> 5;

    const int kLimit = ((i >> 7) + 1) << 7;

    float vals[8];
    float mx = -INFINITY;
    #pragma unroll
    for (int j = 0; j < 2; j++) {
        const int col4 = 4 * t + j * 1024;
        if (col4 <= i) {
            float4 v = *(const float4*)&row[col4];
            const float vv[4] = {v.x, v.y, v.z, v.w};
            #pragma unroll
            for (int k = 0; k < 4; k++) {
                const int col = col4 + k;
                float u = (col <= i) ? fmaf(vv[k], SCALE_, 0.0f) : NEG_;
                vals[j * 4 + k] = u;
                mx = fmaxf(mx, u);
            }
        } else {
            #pragma unroll
            for (int k = 0; k < 4; k++) vals[j * 4 + k] = NEG_;
        }
    }

    __shared__ float red[8];
    #pragma unroll
    for (int o = 16; o > 0; o >>= 1)
        mx = fmaxf(mx, __shfl_xor_sync(0xffffffffu, mx, o));
    if (lane == 0) red[warp] = mx;
    __syncthreads();
    {
        float m = red[lane & 7];
        #pragma unroll
        for (int o = 4; o > 0; o >>= 1)
            m = fmaxf(m, __shfl_xor_sync(0xffffffffu, m, o));
        mx = m;
    }

    float sum = 0.0f;
    #pragma unroll
    for (int j = 0; j < 8; j++) {
        vals[j] = __expf(vals[j] - mx);
        sum += vals[j];
    }
    #pragma unroll
    for (int o = 16; o > 0; o >>= 1)
        sum += __shfl_xor_sync(0xffffffffu, sum, o);
    __syncthreads();
    if (lane == 0) red[warp] = sum;
    __syncthreads();
    {
        float m = red[lane & 7];
        #pragma unroll
        for (int o = 4; o > 0; o >>= 1)
            m += __shfl_xor_sync(0xffffffffu, m, o);
        sum = m;
    }

    const float inv = 1.0f / sum;
    #pragma unroll
    for (int j = 0; j < 2; j++) {
        const int col4 = 4 * t + j * 1024;
        float p0 = vals[j * 4 + 0] * inv;
        float p1 = vals[j * 4 + 1] * inv;
        float p2 = vals[j * 4 + 2] * inv;
        float p3 = vals[j * 4 + 3] * inv;
        *(float4*)&row[col4] = make_float4(p0, p1, p2, p3);
        if (col4 < kLimit)
            *(uint2*)&ph[rowOff + col4] = pack_h4(p0, p1, p2, p3);
    }
}

// ================= launch ======================================================
static void* sym_addr(const void* sym)
{
    void* p = nullptr;
    cudaGetSymbolAddress(&p, sym);
    return p;
}

extern "C" void kernel_launch(void* const* d_in, const int* in_sizes, int n_in,
                              void* d_out, int out_size)
{
    const float* x    = (const float*)d_in[0];
    const int*   pos  = (const int*)  d_in[1];
    const float* wq   = (const float*)d_in[3];
    const float* wk   = (const float*)d_in[4];
    const float* wv   = (const float*)d_in[5];
    const float* wo   = (const float*)d_in[6];

    float* out  = (float*)d_out;
    float* attn = out + (long long)B_ * S_ * H_;

    float* Qf = (float*)sym_addr(g_Q);
    float* Kf = (float*)sym_addr(g_K);
    float* Vf = (float*)sym_addr(g_V);

    fp16* xh   = (fp16*)sym_addr(g_xh);
    fp16* wqT  = (fp16*)sym_addr(g_wqT);
    fp16* wkT  = (fp16*)sym_addr(g_wkT);
    fp16* wvT  = (fp16*)sym_addr(g_wvT);
    fp16* woT  = (fp16*)sym_addr(g_woT);
    fp16* qh   = (fp16*)sym_addr(g_qh);
    fp16* khi  = (fp16*)sym_addr(g_khi);
    fp16* klo  = (fp16*)sym_addr(g_klo);
    fp16* vt   = (fp16*)sym_addr(g_vt);
    fp16* ph   = (fp16*)sym_addr(g_ph);
    fp16* ch   = (fp16*)sym_addr(g_ch);

    // smem: 4 stages, K-chunk 16 (R13 config)
    const int smem1p128 = 4 * (128 * 24 + 128 * 24) * 2;          // 49152
    const int smem1p64  = 4 * (128 * 24 +  64 * 24) * 2;          // 36864
    const int smem2p128 = 4 * (128 * 24 + 2 * 128 * 24) * 2;      // 73728
    cudaFuncSetAttribute(mma_gemm<4,1>, cudaFuncAttributeMaxDynamicSharedMemorySize, smem1p128);
    cudaFuncSetAttribute(mma_gemm<2,1>, cudaFuncAttributeMaxDynamicSharedMemorySize, smem1p64);
    cudaFuncSetAttribute(mma_gemm<4,2>, cudaFuncAttributeMaxDynamicSharedMemorySize, smem2p128);

    const long long SS  = (long long)S_ * S_;
    const long long nSH = (long long)S_ * H_;

    // ---- prep: Q-proj GEMM stays at launch #3 for ncu capture ----
    convert_kernel<<<(unsigned)((nSH / 4 + 255) / 256), 256>>>(
        (const float4*)x, (uint2*)xh, nSH / 4);
    tconvert_kernel<<<dim3(H_ / 32,  H_ / 32), dim3(32, 8)>>>(wq, wqT, H_, H_);
    tconvert_kernel<<<dim3(DH_ / 32, H_ / 32), dim3(32, 8)>>>(wk, wkT, H_, DH_);

    // ---- Q-proj (1-pass): launch #3 ----
    mma_gemm<4,1><<<dim3(H_ / 128, S_ / 128, 1), 256, smem1p128>>>(
        xh, wqT, nullptr, Qf, nullptr, H_, H_, H_, H_, 0, 0, 0, 0);

    tconvert_kernel<<<dim3(DH_ / 32, H_ / 32), dim3(32, 8)>>>(wv, wvT, H_, DH_);
    {
        const long long bS = (long long)(wvT - wkT);
        const long long cS = (long long)(Vf - Kf);
        mma_gemm<2,1><<<dim3(DH_ / 64, S_ / 128, 2), 256, smem1p64>>>(
            xh, wkT, nullptr, Kf, nullptr, H_, H_, H_, DH_, 0, bS, cS, 0);
    }

    // ---- RoPE: Q -> single fp16; K -> hi/lo (for 2-pass QK) ----
    rope_split_kernel<<<(unsigned)(((long long)S_ * NH_ * 32 + 255) / 256), 256>>>(
        Qf, qh, nullptr, pos, NH_, H_);
    rope_split_kernel<<<(unsigned)(((long long)S_ * 32 + 255) / 256), 256>>>(
        Kf, khi, klo, pos, 1, DH_);

    // ---- V transpose (single fp16) ----
    tconvert_kernel<<<dim3(DH_ / 32, S_ / 32), dim3(32, 8)>>>(Vf, vt, S_, DH_);

    // ---- scores: attn_h = Q_h @ K^T (2-pass: Q@Khi + Q@Klo, causal skip) ----
    mma_gemm<4,2><<<dim3(S_ / 128, S_ / 128, NH_), 256, smem2p128>>>(
        qh, khi, klo, attn, nullptr, DH_, H_, DH_, S_, DH_, 0, SS, 1);

    // ---- softmax (analytic causal mask, single fp16 P) ----
    softmax_kernel<<<dim3(S_, NH_), 256>>>(attn, ph);

    // ---- ctx_h = P_h @ V (1-pass, causal K-limit, fp16 ctx epilogue) ----
    mma_gemm<4,1><<<dim3(DH_ / 128, S_ / 128, NH_), 256, smem1p128>>>(
        ph, vt, nullptr, nullptr, ch, S_, S_, S_, H_, SS, 0, DH_, 2);

    // ---- wo transpose, then out = ctx @ w_o (1-pass) ----
    tconvert_kernel<<<dim3(H_ / 32, H_ / 32), dim3(32, 8)>>>(wo, woT, H_, H_);
    mma_gemm<4,1><<<dim3(H_ / 128, S_ / 128, 1), 256, smem1p128>>>(
        ch, woT, nullptr, out, nullptr, H_, H_, H_, H_, 0, 0, 0, 0);
}